// round 1
// baseline (speedup 1.0000x reference)
#include <cuda_runtime.h>
#include <math.h>

// ---------------------------------------------------------------------------
// DynamicResidualStage: 18x (GEMM [6272,512]x[512,512] + bias + tanh-GELU)
// with ChannelGating residual routing at blocks 11,14,17 using anchors 1,4,9.
// Round 1: fp32 SIMT GEMM baseline (correctness + ncu baseline).
// ---------------------------------------------------------------------------

#define M_TOT   6272          // 32*14*14
#define CDIM    512
#define HW      196
#define BATCH   32
#define HIDN    128
#define AANCH   3
#define NELEM   (M_TOT * CDIM)   // 3,211,264

// scratch (allocation-free rule: __device__ globals)
__device__ float g_bufA[NELEM];
__device__ float g_bufB[NELEM];
__device__ float g_anc0[NELEM];
__device__ float g_anc1[NELEM];
__device__ float g_anc2[NELEM];
__device__ float g_pooled[BATCH * CDIM];
__device__ float g_gates[BATCH * AANCH * CDIM];

__device__ __forceinline__ float gelu_tanh(float x) {
    // matches jax.nn.gelu(approximate=True)
    float x3 = x * x * x;
    return 0.5f * x * (1.0f + tanhf(0.7978845608028654f * (x + 0.044715f * x3)));
}

// ---------------------------------------------------------------------------
// GEMM: C[m,n] = gelu( sum_k A[m,k] * W[k,n] + bias[n] )
// A: [6272,512] row-major, W: [512,512] row-major (k-major), exact tiling.
// BM=128, BN=64, BK=16, 256 threads, each computes 8x4.
// ---------------------------------------------------------------------------
#define BM 128
#define BN 64
#define BK 16
#define TM 8
#define TN 4

__global__ __launch_bounds__(256)
void gemm_bias_gelu(const float* __restrict__ A,
                    const float* __restrict__ W,
                    const float* __restrict__ bias,
                    float* __restrict__ C) {
    __shared__ float As[BK][BM];   // A transposed tile
    __shared__ float Bs[BK][BN];

    const int bm = blockIdx.x * BM;
    const int bn = blockIdx.y * BN;
    const int tid = threadIdx.x;
    const int tx = tid & 15;       // n-dir (0..15)
    const int ty = tid >> 4;       // m-dir (0..15)

    // A tile load mapping: 128 rows x 16 cols = 512 float4; 2 float4/thread
    const int arow = tid >> 2;            // 0..63 (two rows: arow, arow+64)
    const int acol = (tid & 3) * 4;       // 0,4,8,12
    // B tile load mapping: 16 rows x 64 cols = 256 float4; 1 float4/thread
    const int brow = tid >> 4;            // 0..15
    const int bcol = (tid & 15) * 4;      // 0..60

    float acc[TM][TN];
#pragma unroll
    for (int i = 0; i < TM; ++i)
#pragma unroll
        for (int j = 0; j < TN; ++j) acc[i][j] = 0.0f;

    for (int k0 = 0; k0 < CDIM; k0 += BK) {
#pragma unroll
        for (int r = 0; r < 2; ++r) {
            const int m = arow + r * 64;
            float4 v = *reinterpret_cast<const float4*>(
                &A[(size_t)(bm + m) * CDIM + k0 + acol]);
            As[acol + 0][m] = v.x;
            As[acol + 1][m] = v.y;
            As[acol + 2][m] = v.z;
            As[acol + 3][m] = v.w;
        }
        *reinterpret_cast<float4*>(&Bs[brow][bcol]) =
            *reinterpret_cast<const float4*>(&W[(size_t)(k0 + brow) * CDIM + bn + bcol]);
        __syncthreads();

#pragma unroll
        for (int k = 0; k < BK; ++k) {
            float ra[TM], rb[TN];
            float4 a0 = *reinterpret_cast<const float4*>(&As[k][ty * TM]);
            float4 a1 = *reinterpret_cast<const float4*>(&As[k][ty * TM + 4]);
            ra[0]=a0.x; ra[1]=a0.y; ra[2]=a0.z; ra[3]=a0.w;
            ra[4]=a1.x; ra[5]=a1.y; ra[6]=a1.z; ra[7]=a1.w;
            float4 b0 = *reinterpret_cast<const float4*>(&Bs[k][tx * TN]);
            rb[0]=b0.x; rb[1]=b0.y; rb[2]=b0.z; rb[3]=b0.w;
#pragma unroll
            for (int i = 0; i < TM; ++i)
#pragma unroll
                for (int j = 0; j < TN; ++j)
                    acc[i][j] = fmaf(ra[i], rb[j], acc[i][j]);
        }
        __syncthreads();
    }

    const int n0 = bn + tx * TN;
    float4 bv = *reinterpret_cast<const float4*>(&bias[n0]);
#pragma unroll
    for (int i = 0; i < TM; ++i) {
        const int m = bm + ty * TM + i;
        float4 o;
        o.x = gelu_tanh(acc[i][0] + bv.x);
        o.y = gelu_tanh(acc[i][1] + bv.y);
        o.z = gelu_tanh(acc[i][2] + bv.z);
        o.w = gelu_tanh(acc[i][3] + bv.w);
        *reinterpret_cast<float4*>(&C[(size_t)m * CDIM + n0]) = o;
    }
}

// ---------------------------------------------------------------------------
// Global mean pool over H*W: pooled[b,c] = mean_hw nx[b,hw,c]
// ---------------------------------------------------------------------------
__global__ void pool_kernel(const float* __restrict__ nx, float* __restrict__ pooled) {
    int idx = blockIdx.x * blockDim.x + threadIdx.x;   // 0..16383
    if (idx >= BATCH * CDIM) return;
    int b = idx >> 9;
    int c = idx & (CDIM - 1);
    const float* p = nx + (size_t)b * HW * CDIM + c;
    float s = 0.0f;
#pragma unroll 4
    for (int i = 0; i < HW; ++i) s += p[(size_t)i * CDIM];
    pooled[idx] = s * (1.0f / (float)HW);
}

// ---------------------------------------------------------------------------
// Router MLP + softmax over anchors. One block per batch element, 128 threads.
// fc1w: [512,128] (k-major), fc2w: [128,1536] (k-major)
// ---------------------------------------------------------------------------
__global__ __launch_bounds__(128)
void mlp_kernel(const float* __restrict__ pooled,
                const float* __restrict__ fc1w, const float* __restrict__ fc1b,
                const float* __restrict__ fc2w, const float* __restrict__ fc2b,
                float* __restrict__ gates) {
    __shared__ float ps[CDIM];
    __shared__ float hs[HIDN];
    __shared__ float lg[AANCH * CDIM];
    const int b = blockIdx.x;
    const int t = threadIdx.x;

    for (int i = t; i < CDIM; i += 128) ps[i] = pooled[b * CDIM + i];
    __syncthreads();

    float acc = fc1b[t];
#pragma unroll 8
    for (int k = 0; k < CDIM; ++k)
        acc = fmaf(ps[k], fc1w[k * HIDN + t], acc);
    hs[t] = gelu_tanh(acc);
    __syncthreads();

    for (int j = t; j < AANCH * CDIM; j += 128) {
        float a2 = fc2b[j];
#pragma unroll 8
        for (int k = 0; k < HIDN; ++k)
            a2 = fmaf(hs[k], fc2w[k * (AANCH * CDIM) + j], a2);
        lg[j] = a2;
    }
    __syncthreads();

    for (int c = t; c < CDIM; c += 128) {
        float l0 = lg[c], l1 = lg[CDIM + c], l2 = lg[2 * CDIM + c];
        float m = fmaxf(l0, fmaxf(l1, l2));
        float e0 = expf(l0 - m), e1 = expf(l1 - m), e2 = expf(l2 - m);
        float inv = 1.0f / (e0 + e1 + e2);
        gates[b * AANCH * CDIM + c]            = e0 * inv;
        gates[b * AANCH * CDIM + CDIM + c]     = e1 * inv;
        gates[b * AANCH * CDIM + 2 * CDIM + c] = e2 * inv;
    }
}

// ---------------------------------------------------------------------------
// Routed residual add: nx += gamma * sum_a gates[b,a,c] * anc_a[b,hw,c]
// float4 over the channel dim.
// ---------------------------------------------------------------------------
__global__ void route_kernel(float* __restrict__ nx,
                             const float* __restrict__ a0,
                             const float* __restrict__ a1,
                             const float* __restrict__ a2,
                             const float* __restrict__ gates,
                             const float* __restrict__ gammas, int tgt) {
    const int i = blockIdx.x * blockDim.x + threadIdx.x;  // float4 index
    const int total = NELEM / 4;
    if (i >= total) return;
    const float gamma = gammas[tgt];
    const int per_b = HW * CDIM / 4;   // 25088
    const int b = i / per_b;
    const int c4 = i & (CDIM / 4 - 1); // channel group within row

    const float4 g0 = *reinterpret_cast<const float4*>(&gates[b * AANCH * CDIM + c4 * 4]);
    const float4 g1 = *reinterpret_cast<const float4*>(&gates[b * AANCH * CDIM + CDIM + c4 * 4]);
    const float4 g2 = *reinterpret_cast<const float4*>(&gates[b * AANCH * CDIM + 2 * CDIM + c4 * 4]);

    float4 v  = reinterpret_cast<float4*>(nx)[i];
    float4 x0 = reinterpret_cast<const float4*>(a0)[i];
    float4 x1 = reinterpret_cast<const float4*>(a1)[i];
    float4 x2 = reinterpret_cast<const float4*>(a2)[i];

    v.x += gamma * (g0.x * x0.x + g1.x * x1.x + g2.x * x2.x);
    v.y += gamma * (g0.y * x0.y + g1.y * x1.y + g2.y * x2.y);
    v.z += gamma * (g0.z * x0.z + g1.z * x1.z + g2.z * x2.z);
    v.w += gamma * (g0.w * x0.w + g1.w * x1.w + g2.w * x2.w);

    reinterpret_cast<float4*>(nx)[i] = v;
}

// ---------------------------------------------------------------------------
// Host orchestration (graph-capturable: launches only)
// ---------------------------------------------------------------------------
extern "C" void kernel_launch(void* const* d_in, const int* in_sizes, int n_in,
                              void* d_out, int out_size) {
    const float* x   = (const float*)d_in[0];   // [32,14,14,512]
    const float* bw  = (const float*)d_in[1];   // [18,512,512]
    const float* bb  = (const float*)d_in[2];   // [18,512]
    const float* f1w = (const float*)d_in[3];   // [3,512,128]
    const float* f1b = (const float*)d_in[4];   // [3,128]
    const float* f2w = (const float*)d_in[5];   // [3,128,1536]
    const float* f2b = (const float*)d_in[6];   // [3,1536]
    const float* gam = (const float*)d_in[7];   // [3]

    float *bufA, *bufB, *anc0, *anc1, *anc2, *pooled, *gates;
    cudaGetSymbolAddress((void**)&bufA,   g_bufA);
    cudaGetSymbolAddress((void**)&bufB,   g_bufB);
    cudaGetSymbolAddress((void**)&anc0,   g_anc0);
    cudaGetSymbolAddress((void**)&anc1,   g_anc1);
    cudaGetSymbolAddress((void**)&anc2,   g_anc2);
    cudaGetSymbolAddress((void**)&pooled, g_pooled);
    cudaGetSymbolAddress((void**)&gates,  g_gates);

    const dim3 gemm_grid(M_TOT / BM, CDIM / BN);   // 49 x 8

    const float* cur = x;
    int tog = 0;
    int tcount = 0;
    for (int i = 0; i < 18; ++i) {
        float* dst;
        if      (i == 1)  dst = anc0;
        else if (i == 4)  dst = anc1;
        else if (i == 9)  dst = anc2;
        else if (i == 17) dst = (float*)d_out;
        else { dst = tog ? bufB : bufA; tog ^= 1; }

        gemm_bias_gelu<<<gemm_grid, 256>>>(cur,
                                           bw + (size_t)i * CDIM * CDIM,
                                           bb + (size_t)i * CDIM,
                                           dst);

        if (i == 11 || i == 14 || i == 17) {
            const int t = tcount++;
            pool_kernel<<<(BATCH * CDIM + 255) / 256, 256>>>(dst, pooled);
            mlp_kernel<<<BATCH, 128>>>(pooled,
                                       f1w + (size_t)t * CDIM * HIDN,
                                       f1b + (size_t)t * HIDN,
                                       f2w + (size_t)t * HIDN * AANCH * CDIM,
                                       f2b + (size_t)t * AANCH * CDIM,
                                       gates);
            route_kernel<<<(NELEM / 4 + 255) / 256, 256>>>(dst, anc0, anc1, anc2,
                                                           gates, gam, t);
        }
        cur = dst;
    }
}

// round 3
// speedup vs baseline: 2.0111x; 2.0111x over previous
#include <cuda_runtime.h>
#include <cuda_bf16.h>
#include <cstdint>
#include <math.h>

// ---------------------------------------------------------------------------
// Round 3: base-arch tensor cores (mma.sync bf16 hi/lo split, 3 products).
// tcgen05 is unavailable: harness compiles via compute_103 (non-'a').
// 18x GEMM [6272,512]x[512,512] + bias + tanh-GELU, gating at 11,14,17.
// ---------------------------------------------------------------------------

#define M_TOT   6272
#define CDIM    512
#define HW      196
#define BATCH   32
#define HIDN    128
#define AANCH   3
#define NELEM   (M_TOT * CDIM)
#define NLAYER  18

// GEMM tiling
#define BM 128
#define BN 64
#define BK 64
#define KSTAGES 8            // 512 / BK
// smem stage layout (128B rows, SW128 swizzle)
#define SA_HI 0
#define SA_LO 16384
#define SB_HI 32768
#define SB_LO 40960
#define STAGE_BYTES 49152
#define SMEM_DYN (1024 + 2 * STAGE_BYTES)

// ---------------------------------------------------------------------------
// Device scratch (allocation-free rule)
// ---------------------------------------------------------------------------
__device__ float g_bufA[NELEM];
__device__ float g_anc0[NELEM];
__device__ float g_anc1[NELEM];
__device__ float g_anc2[NELEM];
__device__ float g_pooled[BATCH * CDIM];
__device__ float g_gates[BATCH * AANCH * CDIM];
__device__ __nv_bfloat16 g_Ahi[2 * NELEM];
__device__ __nv_bfloat16 g_Alo[2 * NELEM];
__device__ __nv_bfloat16 g_Whi[NLAYER * CDIM * CDIM];  // transposed: [l][n][k]
__device__ __nv_bfloat16 g_Wlo[NLAYER * CDIM * CDIM];

// ---------------------------------------------------------------------------
// helpers
// ---------------------------------------------------------------------------
__device__ __forceinline__ uint32_t sw128(uint32_t off) {
    return off ^ ((off >> 3) & 0x70);
}
__device__ __forceinline__ void cpa16(uint32_t s, const void* g) {
    asm volatile("cp.async.cg.shared.global [%0], [%1], 16;" :: "r"(s), "l"(g));
}
__device__ __forceinline__ void cpa_commit() {
    asm volatile("cp.async.commit_group;" ::: "memory");
}
__device__ __forceinline__ void cpa_wait1() {
    asm volatile("cp.async.wait_group 1;" ::: "memory");
}
__device__ __forceinline__ void ldsm_x4(uint32_t& r0, uint32_t& r1, uint32_t& r2,
                                        uint32_t& r3, uint32_t a) {
    asm volatile("ldmatrix.sync.aligned.m8n8.x4.shared.b16 {%0,%1,%2,%3}, [%4];"
                 : "=r"(r0), "=r"(r1), "=r"(r2), "=r"(r3) : "r"(a));
}
__device__ __forceinline__ void mma_bf16(float* c, const uint32_t* a, const uint32_t* b) {
    asm volatile(
        "mma.sync.aligned.m16n8k16.row.col.f32.bf16.bf16.f32 "
        "{%0,%1,%2,%3},{%4,%5,%6,%7},{%8,%9},{%0,%1,%2,%3};"
        : "+f"(c[0]), "+f"(c[1]), "+f"(c[2]), "+f"(c[3])
        : "r"(a[0]), "r"(a[1]), "r"(a[2]), "r"(a[3]), "r"(b[0]), "r"(b[1]));
}
__device__ __forceinline__ float gelu_fast(float x) {
    float u = 0.7978845608028654f * fmaf(0.044715f * x, x * x, x);
    float e = __expf(2.0f * u);
    return 0.5f * x * (1.0f + (1.0f - 2.0f / (e + 1.0f)));
}
__device__ __forceinline__ float gelu_tanh(float x) {
    float x3 = x * x * x;
    return 0.5f * x * (1.0f + tanhf(0.7978845608028654f * (x + 0.044715f * x3)));
}
__device__ __forceinline__ uint32_t pack_bf2(float a, float b) {
    __nv_bfloat162 t = __floats2bfloat162_rn(a, b);
    return *reinterpret_cast<uint32_t*>(&t);
}
__device__ __forceinline__ __nv_bfloat162 split_hi2(float a, float b, float& la, float& lb) {
    __nv_bfloat16 ha = __float2bfloat16(a);
    __nv_bfloat16 hb = __float2bfloat16(b);
    la = a - __bfloat162float(ha);
    lb = b - __bfloat162float(hb);
    __nv_bfloat162 h; h.x = ha; h.y = hb;
    return h;
}

// ---------------------------------------------------------------------------
// HMMA GEMM: out = gelu((Ahi+Alo)@(Bhi+Blo)^T + bias); emits bf16 hi/lo of
// result for the next layer. A: [6272,512] bf16. B(W^T): [512(n),512(k)] bf16.
// 256 threads, 8 warps (4m x 2n), warp tile 32x32, BK=64, 2-stage cp.async.
// ---------------------------------------------------------------------------
__global__ __launch_bounds__(256)
void gemm_hmma(const __nv_bfloat16* __restrict__ aHi, const __nv_bfloat16* __restrict__ aLo,
               const __nv_bfloat16* __restrict__ bHi, const __nv_bfloat16* __restrict__ bLo,
               const float* __restrict__ bias,
               float* __restrict__ out,                    // may be null
               __nv_bfloat16* __restrict__ nHi, __nv_bfloat16* __restrict__ nLo) {
    extern __shared__ char smraw[];
    const uint32_t sbraw = (uint32_t)__cvta_generic_to_shared(smraw);
    const uint32_t sb = (sbraw + 1023u) & ~1023u;

    const int t = threadIdx.x;
    const int lane = t & 31;
    const int w = t >> 5;
    const int wm = (w >> 1) * 32;       // warp m offset in tile
    const int wn = (w & 1) * 32;        // warp n offset in tile
    const int bm = blockIdx.x * BM;
    const int bn = blockIdx.y * BN;

    // ---- stage loader (12 cp.async / thread) ----
    const int a_row = t >> 3;           // 0..31 (x4 passes -> 0..127... see below)
    const int a_c16 = t & 7;

    auto load_stage = [&](int s, int buf) {
        const int k0 = s * BK;
        const uint32_t stg = sb + (uint32_t)buf * STAGE_BYTES;
#pragma unroll
        for (int p = 0; p < 4; ++p) {
            const int row = p * 32 + a_row;                    // 0..127
            const uint32_t so = sw128((uint32_t)row * 128 + a_c16 * 16);
            const size_t gofs = (size_t)(bm + row) * CDIM + k0 + a_c16 * 8;
            cpa16(stg + SA_HI + so, aHi + gofs);
            cpa16(stg + SA_LO + so, aLo + gofs);
        }
#pragma unroll
        for (int p = 0; p < 2; ++p) {
            const int row = p * 32 + a_row;                    // 0..63
            const uint32_t so = sw128((uint32_t)row * 128 + a_c16 * 16);
            const size_t gofs = (size_t)(bn + row) * CDIM + k0 + a_c16 * 8;
            cpa16(stg + SB_HI + so, bHi + gofs);
            cpa16(stg + SB_LO + so, bLo + gofs);
        }
    };

    // ---- per-thread ldmatrix row bases (unswizzled) ----
    // A (.x4): lanes 0-15 -> rows 0-15 @ k+0, lanes 16-31 -> rows 0-15 @ k+16B
    uint32_t a_off[2];
#pragma unroll
    for (int mi = 0; mi < 2; ++mi)
        a_off[mi] = (uint32_t)(wm + mi * 16 + (lane & 15)) * 128 + ((lane >> 4) & 1) * 16;
    // B (.x4): covers 2 n-frags; group g in {0,1}
    uint32_t b_off[2];
#pragma unroll
    for (int g = 0; g < 2; ++g)
        b_off[g] = (uint32_t)(wn + g * 16 + ((lane >> 4) & 1) * 8 + (lane & 7)) * 128 +
                   ((lane >> 3) & 1) * 16;

    float acc[2][4][4];
#pragma unroll
    for (int mi = 0; mi < 2; ++mi)
#pragma unroll
        for (int nf = 0; nf < 4; ++nf)
#pragma unroll
            for (int r = 0; r < 4; ++r) acc[mi][nf][r] = 0.0f;

    load_stage(0, 0); cpa_commit();
    load_stage(1, 1); cpa_commit();

#pragma unroll 1
    for (int s = 0; s < KSTAGES; ++s) {
        cpa_wait1();
        __syncthreads();
        const int buf = s & 1;
        const uint32_t stg = sb + (uint32_t)buf * STAGE_BYTES;

#pragma unroll
        for (int kk = 0; kk < 4; ++kk) {
            const uint32_t kb = kk * 32;
            uint32_t ah[2][4], al[2][4], bh[2][4], bl[2][4];
#pragma unroll
            for (int mi = 0; mi < 2; ++mi) {
                const uint32_t so = sw128(a_off[mi] + kb);
                ldsm_x4(ah[mi][0], ah[mi][1], ah[mi][2], ah[mi][3], stg + SA_HI + so);
                ldsm_x4(al[mi][0], al[mi][1], al[mi][2], al[mi][3], stg + SA_LO + so);
            }
#pragma unroll
            for (int g = 0; g < 2; ++g) {
                const uint32_t so = sw128(b_off[g] + kb);
                ldsm_x4(bh[g][0], bh[g][1], bh[g][2], bh[g][3], stg + SB_HI + so);
                ldsm_x4(bl[g][0], bl[g][1], bl[g][2], bl[g][3], stg + SB_LO + so);
            }
            // product 1: hi*hi
#pragma unroll
            for (int mi = 0; mi < 2; ++mi)
#pragma unroll
                for (int nf = 0; nf < 4; ++nf)
                    mma_bf16(acc[mi][nf], ah[mi], &bh[nf >> 1][(nf & 1) * 2]);
            // product 2: hi*lo
#pragma unroll
            for (int mi = 0; mi < 2; ++mi)
#pragma unroll
                for (int nf = 0; nf < 4; ++nf)
                    mma_bf16(acc[mi][nf], ah[mi], &bl[nf >> 1][(nf & 1) * 2]);
            // product 3: lo*hi
#pragma unroll
            for (int mi = 0; mi < 2; ++mi)
#pragma unroll
                for (int nf = 0; nf < 4; ++nf)
                    mma_bf16(acc[mi][nf], al[mi], &bh[nf >> 1][(nf & 1) * 2]);
        }
        __syncthreads();
        if (s + 2 < KSTAGES) load_stage(s + 2, buf);
        cpa_commit();
    }

    // ---- epilogue: bias + gelu, fp32 (optional) + bf16 hi/lo stores ----
    const int r0 = bm + wm + (lane >> 2);
    const int cbase = bn + wn + (lane & 3) * 2;
#pragma unroll
    for (int mi = 0; mi < 2; ++mi) {
#pragma unroll
        for (int nf = 0; nf < 4; ++nf) {
            const int c = cbase + nf * 8;
            const float2 bv = *reinterpret_cast<const float2*>(&bias[c]);
            const int ra = r0 + mi * 16;
            const int rb = ra + 8;
            float v0 = gelu_fast(acc[mi][nf][0] + bv.x);
            float v1 = gelu_fast(acc[mi][nf][1] + bv.y);
            float v2 = gelu_fast(acc[mi][nf][2] + bv.x);
            float v3 = gelu_fast(acc[mi][nf][3] + bv.y);
            if (out) {
                *reinterpret_cast<float2*>(&out[(size_t)ra * CDIM + c]) = make_float2(v0, v1);
                *reinterpret_cast<float2*>(&out[(size_t)rb * CDIM + c]) = make_float2(v2, v3);
            }
            float l0, l1, l2, l3;
            __nv_bfloat162 h01 = split_hi2(v0, v1, l0, l1);
            __nv_bfloat162 h23 = split_hi2(v2, v3, l2, l3);
            *reinterpret_cast<__nv_bfloat162*>(&nHi[(size_t)ra * CDIM + c]) = h01;
            *reinterpret_cast<__nv_bfloat162*>(&nHi[(size_t)rb * CDIM + c]) = h23;
            *reinterpret_cast<uint32_t*>(&nLo[(size_t)ra * CDIM + c]) = pack_bf2(l0, l1);
            *reinterpret_cast<uint32_t*>(&nLo[(size_t)rb * CDIM + c]) = pack_bf2(l2, l3);
        }
    }
}

// ---------------------------------------------------------------------------
// Preprocessing: x -> bf16 hi/lo ; W -> transposed bf16 hi/lo
// ---------------------------------------------------------------------------
__global__ void convert_x(const float* __restrict__ x,
                          __nv_bfloat16* __restrict__ hi, __nv_bfloat16* __restrict__ lo) {
    int i = blockIdx.x * blockDim.x + threadIdx.x;
    if (i >= NELEM / 4) return;
    float4 v = reinterpret_cast<const float4*>(x)[i];
    float l0, l1, l2, l3;
    __nv_bfloat162 h01 = split_hi2(v.x, v.y, l0, l1);
    __nv_bfloat162 h23 = split_hi2(v.z, v.w, l2, l3);
    uint32_t hp0 = *reinterpret_cast<uint32_t*>(&h01);
    uint32_t hp1 = *reinterpret_cast<uint32_t*>(&h23);
    reinterpret_cast<uint2*>(hi)[i] = make_uint2(hp0, hp1);
    reinterpret_cast<uint2*>(lo)[i] = make_uint2(pack_bf2(l0, l1), pack_bf2(l2, l3));
}

__global__ void convert_w(const float* __restrict__ W,
                          __nv_bfloat16* __restrict__ whi, __nv_bfloat16* __restrict__ wlo) {
    __shared__ float tile[32][33];
    const int l = blockIdx.z;
    const int kt = blockIdx.y * 32;
    const int nt = blockIdx.x * 32;
    const int tx = threadIdx.x, ty = threadIdx.y;
    const size_t lb = (size_t)l * CDIM * CDIM;
#pragma unroll
    for (int q = 0; q < 4; ++q)
        tile[ty + 8 * q][tx] = W[lb + (size_t)(kt + ty + 8 * q) * CDIM + nt + tx];
    __syncthreads();
#pragma unroll
    for (int q = 0; q < 4; ++q) {
        float v = tile[tx][ty + 8 * q];
        __nv_bfloat16 h = __float2bfloat16(v);
        size_t idx = lb + (size_t)(nt + ty + 8 * q) * CDIM + kt + tx;
        whi[idx] = h;
        wlo[idx] = __float2bfloat16(v - __bfloat162float(h));
    }
}

// ---------------------------------------------------------------------------
// Gating: pool, router MLP, routed residual add (+ refresh bf16 hi/lo)
// ---------------------------------------------------------------------------
__global__ void pool_kernel(const float* __restrict__ nx, float* __restrict__ pooled) {
    int idx = blockIdx.x * blockDim.x + threadIdx.x;
    if (idx >= BATCH * CDIM) return;
    int b = idx >> 9;
    int c = idx & (CDIM - 1);
    const float* p = nx + (size_t)b * HW * CDIM + c;
    float s = 0.0f;
#pragma unroll 4
    for (int i = 0; i < HW; ++i) s += p[(size_t)i * CDIM];
    pooled[idx] = s * (1.0f / (float)HW);
}

__global__ __launch_bounds__(128)
void mlp_kernel(const float* __restrict__ pooled,
                const float* __restrict__ fc1w, const float* __restrict__ fc1b,
                const float* __restrict__ fc2w, const float* __restrict__ fc2b,
                float* __restrict__ gates) {
    __shared__ float ps[CDIM];
    __shared__ float hs[HIDN];
    __shared__ float lg[AANCH * CDIM];
    const int b = blockIdx.x;
    const int t = threadIdx.x;

    for (int i = t; i < CDIM; i += 128) ps[i] = pooled[b * CDIM + i];
    __syncthreads();

    float acc = fc1b[t];
#pragma unroll 8
    for (int k = 0; k < CDIM; ++k)
        acc = fmaf(ps[k], fc1w[k * HIDN + t], acc);
    hs[t] = gelu_tanh(acc);
    __syncthreads();

    for (int j = t; j < AANCH * CDIM; j += 128) {
        float a2 = fc2b[j];
#pragma unroll 8
        for (int k = 0; k < HIDN; ++k)
            a2 = fmaf(hs[k], fc2w[k * (AANCH * CDIM) + j], a2);
        lg[j] = a2;
    }
    __syncthreads();

    for (int c = t; c < CDIM; c += 128) {
        float l0 = lg[c], l1 = lg[CDIM + c], l2 = lg[2 * CDIM + c];
        float m = fmaxf(l0, fmaxf(l1, l2));
        float e0 = expf(l0 - m), e1 = expf(l1 - m), e2 = expf(l2 - m);
        float inv = 1.0f / (e0 + e1 + e2);
        gates[b * AANCH * CDIM + c]            = e0 * inv;
        gates[b * AANCH * CDIM + CDIM + c]     = e1 * inv;
        gates[b * AANCH * CDIM + 2 * CDIM + c] = e2 * inv;
    }
}

__global__ void route_kernel(float* __restrict__ nx,
                             const float* __restrict__ a0,
                             const float* __restrict__ a1,
                             const float* __restrict__ a2,
                             const float* __restrict__ gates,
                             const float* __restrict__ gammas, int tgt,
                             __nv_bfloat16* __restrict__ nhi,
                             __nv_bfloat16* __restrict__ nlo) {
    const int i = blockIdx.x * blockDim.x + threadIdx.x;
    if (i >= NELEM / 4) return;
    const float gamma = gammas[tgt];
    const int per_b = HW * CDIM / 4;
    const int b = i / per_b;
    const int c4 = i & (CDIM / 4 - 1);

    const float4 g0 = *reinterpret_cast<const float4*>(&gates[b * AANCH * CDIM + c4 * 4]);
    const float4 g1 = *reinterpret_cast<const float4*>(&gates[b * AANCH * CDIM + CDIM + c4 * 4]);
    const float4 g2 = *reinterpret_cast<const float4*>(&gates[b * AANCH * CDIM + 2 * CDIM + c4 * 4]);

    float4 v  = reinterpret_cast<float4*>(nx)[i];
    float4 x0 = reinterpret_cast<const float4*>(a0)[i];
    float4 x1 = reinterpret_cast<const float4*>(a1)[i];
    float4 x2 = reinterpret_cast<const float4*>(a2)[i];

    v.x += gamma * (g0.x * x0.x + g1.x * x1.x + g2.x * x2.x);
    v.y += gamma * (g0.y * x0.y + g1.y * x1.y + g2.y * x2.y);
    v.z += gamma * (g0.z * x0.z + g1.z * x1.z + g2.z * x2.z);
    v.w += gamma * (g0.w * x0.w + g1.w * x1.w + g2.w * x2.w);

    reinterpret_cast<float4*>(nx)[i] = v;

    float l0, l1, l2, l3;
    __nv_bfloat162 h01 = split_hi2(v.x, v.y, l0, l1);
    __nv_bfloat162 h23 = split_hi2(v.z, v.w, l2, l3);
    uint32_t hp0 = *reinterpret_cast<uint32_t*>(&h01);
    uint32_t hp1 = *reinterpret_cast<uint32_t*>(&h23);
    reinterpret_cast<uint2*>(nhi)[i] = make_uint2(hp0, hp1);
    reinterpret_cast<uint2*>(nlo)[i] = make_uint2(pack_bf2(l0, l1), pack_bf2(l2, l3));
}

// ---------------------------------------------------------------------------
// Host orchestration (graph-capturable)
// ---------------------------------------------------------------------------
extern "C" void kernel_launch(void* const* d_in, const int* in_sizes, int n_in,
                              void* d_out, int out_size) {
    const float* x   = (const float*)d_in[0];
    const float* bw  = (const float*)d_in[1];
    const float* bb  = (const float*)d_in[2];
    const float* f1w = (const float*)d_in[3];
    const float* f1b = (const float*)d_in[4];
    const float* f2w = (const float*)d_in[5];
    const float* f2b = (const float*)d_in[6];
    const float* gam = (const float*)d_in[7];

    float *bufA, *anc0, *anc1, *anc2, *pooled, *gates;
    __nv_bfloat16 *ahi, *alo, *whi, *wlo;
    cudaGetSymbolAddress((void**)&bufA,   g_bufA);
    cudaGetSymbolAddress((void**)&anc0,   g_anc0);
    cudaGetSymbolAddress((void**)&anc1,   g_anc1);
    cudaGetSymbolAddress((void**)&anc2,   g_anc2);
    cudaGetSymbolAddress((void**)&pooled, g_pooled);
    cudaGetSymbolAddress((void**)&gates,  g_gates);
    cudaGetSymbolAddress((void**)&ahi,    g_Ahi);
    cudaGetSymbolAddress((void**)&alo,    g_Alo);
    cudaGetSymbolAddress((void**)&whi,    g_Whi);
    cudaGetSymbolAddress((void**)&wlo,    g_Wlo);

    cudaFuncSetAttribute(gemm_hmma, cudaFuncAttributeMaxDynamicSharedMemorySize, SMEM_DYN);

    convert_w<<<dim3(CDIM / 32, CDIM / 32, NLAYER), dim3(32, 8)>>>(bw, whi, wlo);
    convert_x<<<(NELEM / 4 + 255) / 256, 256>>>(x, ahi, alo);

    const dim3 gemm_grid(M_TOT / BM, CDIM / BN);   // 49 x 8
    int tcount = 0;
    for (int i = 0; i < NLAYER; ++i) {
        float* dst;                        // fp32 output only when needed
        if      (i == 1)  dst = anc0;
        else if (i == 4)  dst = anc1;
        else if (i == 9)  dst = anc2;
        else if (i == 17) dst = (float*)d_out;
        else if (i == 11 || i == 14) dst = bufA;
        else              dst = nullptr;

        const int inS  = i & 1;
        const int outS = (i + 1) & 1;
        __nv_bfloat16* nhi = ahi + (size_t)outS * NELEM;
        __nv_bfloat16* nlo = alo + (size_t)outS * NELEM;

        gemm_hmma<<<gemm_grid, 256, SMEM_DYN>>>(
            ahi + (size_t)inS * NELEM, alo + (size_t)inS * NELEM,
            whi + (size_t)i * CDIM * CDIM, wlo + (size_t)i * CDIM * CDIM,
            bb + (size_t)i * CDIM, dst, nhi, nlo);

        if (i == 11 || i == 14 || i == 17) {
            const int tt = tcount++;
            pool_kernel<<<(BATCH * CDIM + 255) / 256, 256>>>(dst, pooled);
            mlp_kernel<<<BATCH, 128>>>(pooled,
                                       f1w + (size_t)tt * CDIM * HIDN,
                                       f1b + (size_t)tt * HIDN,
                                       f2w + (size_t)tt * HIDN * AANCH * CDIM,
                                       f2b + (size_t)tt * AANCH * CDIM,
                                       gates);
            route_kernel<<<(NELEM / 4 + 255) / 256, 256>>>(dst, anc0, anc1, anc2,
                                                           gates, gam, tt, nhi, nlo);
        }
    }
}